// round 12
// baseline (speedup 1.0000x reference)
#include <cuda_runtime.h>
#include <cstdint>

#define TILE_WORDS 8192
#define NTHREADS   512
#define WPT        (TILE_WORDS / NTHREADS)   // 16 words per thread
#define VECS       (WPT / 4)                 // 4 uint4 per thread
#define NWARPS     (NTHREADS / 32)

// constants from the reference (only the h2 stream reaches the output)
#define FMIX_C1 2246822507u
#define FMIX_C2 3266489909u
#define POS_B   374761393u
#define SEED    608135816u

__device__ __forceinline__ uint32_t fmix32(uint32_t x) {   // scalar epilogue
    x ^= x >> 16; x *= FMIX_C1;
    x ^= x >> 13; x *= FMIX_C2;
    x ^= x >> 16;
    return x;
}

// fmix32 with ONLY the middle shift moved to the fma pipe (IMAD.HI).
// m19 = 2^19 arrives as a runtime arg so ptxas can't fold it back to SHF.
__device__ __forceinline__ uint32_t fmix32_bal(uint32_t x, uint32_t m19) {
    x ^= x >> 16;             // SHF + LOP3 (alu)
    x *= FMIX_C1;             // IMAD (fma)
    x ^= __umulhi(x, m19);    // IMAD.HI (fma) + LOP3 : x >> 13
    x *= FMIX_C2;             // IMAD (fma)
    x ^= x >> 16;             // SHF + LOP3 (alu)
    return x;
}

// One word, h2 stream only (output = int64 hash truncated to int32 = h2_final).
__device__ __forceinline__ void hash_step(uint32_t v, uint32_t i, uint32_t s2,
                                          uint32_t one, uint32_t m19,
                                          uint32_t& acc) {
    uint32_t a2 = i * POS_B + s2;                 // IMAD  (fma)
    uint32_t r2 = __funnelshift_l(i, i, 13);      // SHF   (alu)
    uint32_t x  = fmix32_bal(v ^ a2 ^ r2, m19);   // LOP3 fuses v^a^r
    acc = x * one + acc;                          // IMAD  (fma) accumulate
}

__global__ void __launch_bounds__(NTHREADS, 4)
hash_tiles_kernel(const uint32_t* __restrict__ in,
                  float* __restrict__ out,
                  uint32_t n, uint32_t one, uint32_t m19) {
    const uint32_t tile = blockIdx.x;
    const uint32_t base = tile * TILE_WORDS;
    const uint32_t tid  = threadIdx.x;

    const uint32_t s2 = (uint32_t)((SEED * 2654435761u) ^ 3735928559u);

    uint32_t h2a = 0u, h2b = 0u;   // dual accumulators (wrapping add commutes)

    if (base + TILE_WORDS <= n) {
        // fast path: full tile; 4 coalesced uint4 loads per thread, batched up
        // front (evict-first: single-touch streaming data)
        const uint4* inv = reinterpret_cast<const uint4*>(in + base);
        uint4 v[VECS];
        #pragma unroll
        for (int j = 0; j < VECS; ++j) {
            v[j] = __ldcs(&inv[(uint32_t)j * NTHREADS + tid]);
        }
        #pragma unroll
        for (int j = 0; j < VECS; ++j) {
            uint32_t i0 = base + ((uint32_t)j * NTHREADS + tid) * 4u;
            hash_step(v[j].x, i0 + 0u, s2, one, m19, h2a);
            hash_step(v[j].y, i0 + 1u, s2, one, m19, h2b);
            hash_step(v[j].z, i0 + 2u, s2, one, m19, h2a);
            hash_step(v[j].w, i0 + 3u, s2, one, m19, h2b);
        }
    } else {
        // ragged tail tile: scalar guarded (not hit for n % TILE == 0)
        for (uint32_t w = tid; w < TILE_WORDS; w += NTHREADS) {
            uint32_t i = base + w;
            if (i < n) {
                uint32_t a2 = i * POS_B + s2;
                uint32_t r2 = __funnelshift_l(i, i, 13);
                h2a += fmix32(in[i] ^ a2 ^ r2);
            }
        }
    }

    uint32_t h2 = h2a + h2b;

    // warp reduction (wrapping uint32 adds)
    #pragma unroll
    for (int o = 16; o > 0; o >>= 1) {
        h2 += __shfl_down_sync(0xffffffffu, h2, o);
    }

    __shared__ uint32_t sh2[NWARPS];
    if ((tid & 31u) == 0u) sh2[tid >> 5] = h2;
    __syncthreads();

    if (tid == 0) {
        uint32_t b = 0u;
        #pragma unroll
        for (int w = 0; w < NWARPS; ++w) b += sh2[w];
        uint32_t nbytes = n * 4u;          // wrapping, matches (n*4) & 0xFFFFFFFF
        b = fmix32(b ^ nbytes);            // h2_final = low word of int64 hash
        // Output = int64 hash truncated to int32, value-cast to float32.
        out[tile] = (float)(int32_t)b;
    }
}

extern "C" void kernel_launch(void* const* d_in, const int* in_sizes, int n_in,
                              void* d_out, int out_size) {
    const uint32_t* in = (const uint32_t*)d_in[0];
    float* out = (float*)d_out;
    uint32_t n = (uint32_t)in_sizes[0];
    uint32_t n_tiles = (n + TILE_WORDS - 1) / TILE_WORDS;
    hash_tiles_kernel<<<n_tiles, NTHREADS>>>(in, out, n, 1u, 1u << 19);
}

// round 13
// speedup vs baseline: 1.0323x; 1.0323x over previous
#include <cuda_runtime.h>
#include <cstdint>

#define TILE_WORDS 8192
#define NTHREADS   512
#define WPT        (TILE_WORDS / NTHREADS)   // 16 words per thread
#define VECS       (WPT / 4)                 // 4 uint4 per thread
#define NWARPS     (NTHREADS / 32)

// constants from the reference (only the h2 stream reaches the output)
#define FMIX_C1 2246822507u
#define FMIX_C2 3266489909u
#define POS_B   374761393u
#define SEED    608135816u

__device__ __forceinline__ uint32_t fmix32(uint32_t x) {
    x ^= x >> 16; x *= FMIX_C1;
    x ^= x >> 13; x *= FMIX_C2;
    x ^= x >> 16;
    return x;
}

// One word, h2 stream only (output = int64 hash truncated to int32 = h2_final).
// fmix chain stays entirely on the alu pipe (R9/R12 showed any fma<->alu hop
// lengthens the serial chain and regresses); only the off-chain accumulate
// rides the slack fma pipe via IMAD with a runtime-opaque multiplier of 1.
__device__ __forceinline__ void hash_step(uint32_t v, uint32_t i, uint32_t s2,
                                          uint32_t one, uint32_t& acc) {
    uint32_t a2 = i * POS_B + s2;                 // IMAD  (fma)
    uint32_t r2 = __funnelshift_l(i, i, 13);      // SHF   (alu)
    uint32_t x  = fmix32(v ^ a2 ^ r2);            // LOP3 fuses v^a^r
    acc = x * one + acc;                          // IMAD  (fma) accumulate
}

__global__ void __launch_bounds__(NTHREADS, 4)
hash_tiles_kernel(const uint32_t* __restrict__ in,
                  float* __restrict__ out,
                  uint32_t n, uint32_t one) {
    const uint32_t tile = blockIdx.x;
    const uint32_t base = tile * TILE_WORDS;
    const uint32_t tid  = threadIdx.x;

    const uint32_t s2 = (uint32_t)((SEED * 2654435761u) ^ 3735928559u);

    uint32_t h2a = 0u, h2b = 0u;   // dual accumulators (wrapping add commutes)

    if (base + TILE_WORDS <= n) {
        // fast path: full tile; 4 coalesced uint4 loads per thread, batched up
        // front (evict-first: single-touch streaming data)
        const uint4* inv = reinterpret_cast<const uint4*>(in + base);
        uint4 v[VECS];
        #pragma unroll
        for (int j = 0; j < VECS; ++j) {
            v[j] = __ldcs(&inv[(uint32_t)j * NTHREADS + tid]);
        }
        #pragma unroll
        for (int j = 0; j < VECS; ++j) {
            uint32_t i0 = base + ((uint32_t)j * NTHREADS + tid) * 4u;
            hash_step(v[j].x, i0 + 0u, s2, one, h2a);
            hash_step(v[j].y, i0 + 1u, s2, one, h2b);
            hash_step(v[j].z, i0 + 2u, s2, one, h2a);
            hash_step(v[j].w, i0 + 3u, s2, one, h2b);
        }
    } else {
        // ragged tail tile: scalar guarded (not hit for n % TILE == 0)
        for (uint32_t w = tid; w < TILE_WORDS; w += NTHREADS) {
            uint32_t i = base + w;
            if (i < n) {
                uint32_t a2 = i * POS_B + s2;
                uint32_t r2 = __funnelshift_l(i, i, 13);
                h2a += fmix32(in[i] ^ a2 ^ r2);
            }
        }
    }

    uint32_t h2 = h2a + h2b;

    // warp reduction (wrapping uint32 adds)
    #pragma unroll
    for (int o = 16; o > 0; o >>= 1) {
        h2 += __shfl_down_sync(0xffffffffu, h2, o);
    }

    __shared__ uint32_t sh2[NWARPS];
    if ((tid & 31u) == 0u) sh2[tid >> 5] = h2;
    __syncthreads();

    if (tid == 0) {
        uint32_t b = 0u;
        #pragma unroll
        for (int w = 0; w < NWARPS; ++w) b += sh2[w];
        uint32_t nbytes = n * 4u;          // wrapping, matches (n*4) & 0xFFFFFFFF
        b = fmix32(b ^ nbytes);            // h2_final = low word of int64 hash
        // Output = int64 hash truncated to int32, value-cast to float32.
        out[tile] = (float)(int32_t)b;
    }
}

extern "C" void kernel_launch(void* const* d_in, const int* in_sizes, int n_in,
                              void* d_out, int out_size) {
    const uint32_t* in = (const uint32_t*)d_in[0];
    float* out = (float*)d_out;
    uint32_t n = (uint32_t)in_sizes[0];
    uint32_t n_tiles = (n + TILE_WORDS - 1) / TILE_WORDS;
    hash_tiles_kernel<<<n_tiles, NTHREADS>>>(in, out, n, 1u);
}

// round 14
// speedup vs baseline: 1.0738x; 1.0402x over previous
#include <cuda_runtime.h>
#include <cstdint>

#define TILE_WORDS 8192
#define NTHREADS   512
#define WPT        (TILE_WORDS / NTHREADS)   // 16 words per thread
#define VECS       (WPT / 4)                 // 4 uint4 per thread
#define NWARPS     (NTHREADS / 32)

// constants from the reference (only the h2 stream reaches the output)
#define FMIX_C1 2246822507u
#define FMIX_C2 3266489909u
#define POS_B   374761393u
#define SEED    608135816u

__device__ __forceinline__ uint32_t fmix32(uint32_t x) {
    x ^= x >> 16; x *= FMIX_C1;
    x ^= x >> 13; x *= FMIX_C2;
    x ^= x >> 16;
    return x;
}

// One word with PRE-DECOMPOSED position terms. For i = i0 + k (i0 % 4 == 0,
// k in 0..3):
//   rotl(i,13)      = rotl(i0,13) + (k<<13)      (disjoint bits, OR == ADD)
//   i*POS_B + s2    = (i0*POS_B + s2) + k*POS_B  (mod 2^32)
// so the per-word cost is two constant adds (ptxas alternates IMAD/IADD3
// across pipes) instead of IADD+IMAD+SHF; the per-word SHF vanishes.
// The fmix chain stays entirely on the alu pipe (R9/R12: cross-pipe hops in
// the serial chain regress). Accumulate rides the fma pipe via opaque IMAD.
__device__ __forceinline__ void hash_step_k(uint32_t v, uint32_t A0, uint32_t R0,
                                            uint32_t kposb, uint32_t k13,
                                            uint32_t one, uint32_t& acc) {
    uint32_t a2 = A0 + kposb;                     // IMAD/IADD3 (off-chain)
    uint32_t r2 = R0 + k13;                       // IADD3/IMAD (off-chain)
    uint32_t x  = fmix32(v ^ a2 ^ r2);            // LOP3 fuses v^a^r
    acc = x * one + acc;                          // IMAD (fma) accumulate
}

__global__ void __launch_bounds__(NTHREADS, 4)
hash_tiles_kernel(const uint32_t* __restrict__ in,
                  float* __restrict__ out,
                  uint32_t n, uint32_t one) {
    const uint32_t tile = blockIdx.x;
    const uint32_t base = tile * TILE_WORDS;
    const uint32_t tid  = threadIdx.x;

    const uint32_t s2 = (uint32_t)((SEED * 2654435761u) ^ 3735928559u);

    uint32_t h2a = 0u, h2b = 0u;   // dual accumulators (wrapping add commutes)

    if (base + TILE_WORDS <= n) {
        // fast path: full tile; 4 coalesced uint4 loads per thread, batched up
        // front (evict-first: single-touch streaming data)
        const uint4* inv = reinterpret_cast<const uint4*>(in + base);
        uint4 v[VECS];
        #pragma unroll
        for (int j = 0; j < VECS; ++j) {
            v[j] = __ldcs(&inv[(uint32_t)j * NTHREADS + tid]);
        }
        #pragma unroll
        for (int j = 0; j < VECS; ++j) {
            uint32_t i0 = base + ((uint32_t)j * NTHREADS + tid) * 4u;  // %4==0
            uint32_t A0 = i0 * POS_B + s2;              // 1 IMAD per burst
            uint32_t R0 = __funnelshift_l(i0, i0, 13);  // 1 SHF  per burst
            hash_step_k(v[j].x, A0, R0, 0u * POS_B, 0u << 13, one, h2a);
            hash_step_k(v[j].y, A0, R0, 1u * POS_B, 1u << 13, one, h2b);
            hash_step_k(v[j].z, A0, R0, 2u * POS_B, 2u << 13, one, h2a);
            hash_step_k(v[j].w, A0, R0, 3u * POS_B, 3u << 13, one, h2b);
        }
    } else {
        // ragged tail tile: scalar guarded (not hit for n % TILE == 0)
        for (uint32_t w = tid; w < TILE_WORDS; w += NTHREADS) {
            uint32_t i = base + w;
            if (i < n) {
                uint32_t a2 = i * POS_B + s2;
                uint32_t r2 = __funnelshift_l(i, i, 13);
                h2a += fmix32(in[i] ^ a2 ^ r2);
            }
        }
    }

    uint32_t h2 = h2a + h2b;

    // warp reduction (wrapping uint32 adds)
    #pragma unroll
    for (int o = 16; o > 0; o >>= 1) {
        h2 += __shfl_down_sync(0xffffffffu, h2, o);
    }

    __shared__ uint32_t sh2[NWARPS];
    if ((tid & 31u) == 0u) sh2[tid >> 5] = h2;
    __syncthreads();

    if (tid == 0) {
        uint32_t b = 0u;
        #pragma unroll
        for (int w = 0; w < NWARPS; ++w) b += sh2[w];
        uint32_t nbytes = n * 4u;          // wrapping, matches (n*4) & 0xFFFFFFFF
        b = fmix32(b ^ nbytes);            // h2_final = low word of int64 hash
        // Output = int64 hash truncated to int32, value-cast to float32.
        out[tile] = (float)(int32_t)b;
    }
}

extern "C" void kernel_launch(void* const* d_in, const int* in_sizes, int n_in,
                              void* d_out, int out_size) {
    const uint32_t* in = (const uint32_t*)d_in[0];
    float* out = (float*)d_out;
    uint32_t n = (uint32_t)in_sizes[0];
    uint32_t n_tiles = (n + TILE_WORDS - 1) / TILE_WORDS;
    hash_tiles_kernel<<<n_tiles, NTHREADS>>>(in, out, n, 1u);
}

// round 15
// speedup vs baseline: 1.0801x; 1.0059x over previous
#include <cuda_runtime.h>
#include <cstdint>

#define TILE_WORDS 8192
#define NTHREADS   512
#define WPT        (TILE_WORDS / NTHREADS)   // 16 words per thread
#define VECS       (WPT / 4)                 // 4 uint4 per thread
#define NWARPS     (NTHREADS / 32)

// constants from the reference (only the h2 stream reaches the output)
#define FMIX_C1 2246822507u
#define FMIX_C2 3266489909u
#define POS_B   374761393u
#define SEED    608135816u

__device__ __forceinline__ uint32_t fmix32(uint32_t x) {
    x ^= x >> 16; x *= FMIX_C1;
    x ^= x >> 13; x *= FMIX_C2;
    x ^= x >> 16;
    return x;
}

// One word with PRE-DECOMPOSED position terms. For i = i0 + k (i0 % 4 == 0,
// k in 0..3):
//   rotl(i,13)      = rotl(i0,13) + (k<<13)      (disjoint bits, OR == ADD)
//   i*POS_B + s2    = (i0*POS_B + s2) + k*POS_B  (mod 2^32)
// The two per-word adds are forced onto the fma pipe as opaque IMADs
// (multiplier `one` is a runtime arg): they are off the serial chain (index-
// only, scheduled long before the loaded value arrives), so only their issue
// slots matter — and the fma pipe has slack (23.6% vs alu 61.5% in R14).
// The fmix chain itself stays entirely on the alu pipe (R9/R12: cross-pipe
// hops inside the serial chain regress).
__device__ __forceinline__ void hash_step_k(uint32_t v, uint32_t A0, uint32_t R0,
                                            uint32_t kposb, uint32_t k13,
                                            uint32_t one, uint32_t& acc) {
    uint32_t a2 = A0 * one + kposb;               // IMAD (fma, off-chain)
    uint32_t r2 = R0 * one + k13;                 // IMAD (fma, off-chain)
    uint32_t x  = fmix32(v ^ a2 ^ r2);            // LOP3 fuses v^a^r
    acc = x * one + acc;                          // IMAD (fma) accumulate
}

__global__ void __launch_bounds__(NTHREADS, 4)
hash_tiles_kernel(const uint32_t* __restrict__ in,
                  float* __restrict__ out,
                  uint32_t n, uint32_t one) {
    const uint32_t tile = blockIdx.x;
    const uint32_t base = tile * TILE_WORDS;
    const uint32_t tid  = threadIdx.x;

    const uint32_t s2 = (uint32_t)((SEED * 2654435761u) ^ 3735928559u);

    uint32_t h2a = 0u, h2b = 0u;   // dual accumulators (wrapping add commutes)

    if (base + TILE_WORDS <= n) {
        // fast path: full tile; 4 coalesced uint4 loads per thread, batched up
        // front (evict-first: single-touch streaming data)
        const uint4* inv = reinterpret_cast<const uint4*>(in + base);
        uint4 v[VECS];
        #pragma unroll
        for (int j = 0; j < VECS; ++j) {
            v[j] = __ldcs(&inv[(uint32_t)j * NTHREADS + tid]);
        }
        #pragma unroll
        for (int j = 0; j < VECS; ++j) {
            uint32_t i0 = base + ((uint32_t)j * NTHREADS + tid) * 4u;  // %4==0
            uint32_t A0 = i0 * POS_B + s2;              // 1 IMAD per burst
            uint32_t R0 = __funnelshift_l(i0, i0, 13);  // 1 SHF  per burst
            hash_step_k(v[j].x, A0, R0, 0u * POS_B, 0u << 13, one, h2a);
            hash_step_k(v[j].y, A0, R0, 1u * POS_B, 1u << 13, one, h2b);
            hash_step_k(v[j].z, A0, R0, 2u * POS_B, 2u << 13, one, h2a);
            hash_step_k(v[j].w, A0, R0, 3u * POS_B, 3u << 13, one, h2b);
        }
    } else {
        // ragged tail tile: scalar guarded (not hit for n % TILE == 0)
        for (uint32_t w = tid; w < TILE_WORDS; w += NTHREADS) {
            uint32_t i = base + w;
            if (i < n) {
                uint32_t a2 = i * POS_B + s2;
                uint32_t r2 = __funnelshift_l(i, i, 13);
                h2a += fmix32(in[i] ^ a2 ^ r2);
            }
        }
    }

    uint32_t h2 = h2a + h2b;

    // warp reduction (wrapping uint32 adds)
    #pragma unroll
    for (int o = 16; o > 0; o >>= 1) {
        h2 += __shfl_down_sync(0xffffffffu, h2, o);
    }

    __shared__ uint32_t sh2[NWARPS];
    if ((tid & 31u) == 0u) sh2[tid >> 5] = h2;
    __syncthreads();

    if (tid == 0) {
        uint32_t b = 0u;
        #pragma unroll
        for (int w = 0; w < NWARPS; ++w) b += sh2[w];
        uint32_t nbytes = n * 4u;          // wrapping, matches (n*4) & 0xFFFFFFFF
        b = fmix32(b ^ nbytes);            // h2_final = low word of int64 hash
        // Output = int64 hash truncated to int32, value-cast to float32.
        out[tile] = (float)(int32_t)b;
    }
}

extern "C" void kernel_launch(void* const* d_in, const int* in_sizes, int n_in,
                              void* d_out, int out_size) {
    const uint32_t* in = (const uint32_t*)d_in[0];
    float* out = (float*)d_out;
    uint32_t n = (uint32_t)in_sizes[0];
    uint32_t n_tiles = (n + TILE_WORDS - 1) / TILE_WORDS;
    hash_tiles_kernel<<<n_tiles, NTHREADS>>>(in, out, n, 1u);
}